// round 13
// baseline (speedup 1.0000x reference)
#include <cuda_runtime.h>
#include <cuda_bf16.h>
#include <cstdint>

// ---------------------------------------------------------------------------
// cls_model, persistent single-kernel. B=4, N=16384, C=3, N_C=1024, K=32
// R11: t0-register-cached work scanning (kills the ~100K-cycle volatile
//      skip-scan found in R10's post-mortem), FPS warp-shuffle reduce.
// Phases: P0 FPS (progressive pub) || pool-zero || L2 warm
//         P1 KNN+conv1..4 ; barA ; P2 conv5+maxpool ; barB ;
//         P3 fc1 ; barC ; P4 fc2 ; barD ; P5 fc3 -> out
// ---------------------------------------------------------------------------

#define NB 4
#define NPTS 16384
#define NC 1024
#define KNN 32
#define G 128
#define NCONS 124
#define CAP 1024

// ---- device scratch (no allocations allowed) ----
__device__ int      g_cnt[NB];
__device__ float    g_cent[NB * NC * 3];
__device__ float    g_h4[(size_t)NB * NC * KNN * 128];
__device__ int      g_pool[NB * 1024];
__device__ float    g_a1[NB * 512];
__device__ float    g_a2[NB * 256];
__device__ float    g_sink[G];
__device__ volatile int g_fps_pub[NB];
__device__ volatile int g_fps_done[NB];
__device__ unsigned g_bar_arrive = 0;
__device__ unsigned g_bar_gen = 0;

static __device__ __forceinline__ unsigned f_ord(float f) {
    unsigned b = __float_as_uint(f);
    return b ^ ((unsigned)(((int)b) >> 31) | 0x80000000u);
}

static __device__ __forceinline__ void grid_bar() {
    __syncthreads();
    if (threadIdx.x == 0) {
        unsigned gen = ((volatile unsigned*)&g_bar_gen)[0];
        __threadfence();
        unsigned a = atomicAdd(&g_bar_arrive, 1u);
        if (a == (unsigned)G - 1u) {
            g_bar_arrive = 0u;
            __threadfence();
            atomicAdd(&g_bar_gen, 1u);
        } else {
            while (((volatile unsigned*)&g_bar_gen)[0] == gen) __nanosleep(32);
        }
        __threadfence();
    }
    __syncthreads();
}

// SMEM overlay (phases sequential; offsets in bytes):
//  FPS:  seen[512]            @0
//  KNN:  hist[4096]i @0 (16384) | cand[CAP]u64 @16384 (8192) | part[512]i @24576
//  conv: Ha[32][65] @0 | Hb[32][65] @8320 | wT[64*65] @17408 | P[32][4] @34048
//        W4[128*65] @8320 (Hb/wT dead by conv4)
//  P2:   H4[32*128] @0 | W[32*129] @16384 | S[16*32] @32896
#define SH_BYTES 41728
__shared__ __align__(16) char SH[SH_BYTES];

__global__ __launch_bounds__(512) void k_all(
    const float* __restrict__ x,    const int* __restrict__ far0,
    const float* __restrict__ w1,  const float* __restrict__ b1,
    const float* __restrict__ w2,  const float* __restrict__ b2,
    const float* __restrict__ w3,  const float* __restrict__ b3,
    const float* __restrict__ w4,  const float* __restrict__ b4,
    const float* __restrict__ w5,  const float* __restrict__ b5,
    const float* __restrict__ fw1, const float* __restrict__ fb1,
    const float* __restrict__ fw2, const float* __restrict__ fb2,
    const float* __restrict__ fw3, const float* __restrict__ fb3,
    float* __restrict__ out) {
    const int bid = blockIdx.x;
    const int t = threadIdx.x;
    const int lane = t & 31, wrp = t >> 5;

    __shared__ float cc[3];
    __shared__ float rd[16]; __shared__ int rn[16];
    __shared__ float rx[16], ry[16], rz[16];
    __shared__ int sdone;
    __shared__ int wlist[KNN];
    __shared__ int s_u, s_B, s_m, s_sure, s_cand;

    // ================= P0/P1 overlapped ===================================
    if (bid < NB) {
        // ---------------- FPS producer (bit-exact vs reference) -----------
        const int b = bid;
        const float* xb = x + (size_t)b * NPTS * 3;
        unsigned* seen = (unsigned*)SH;

        if (t == 0) { g_fps_done[b] = 0; g_fps_pub[b] = 0; __threadfence(); }

        float px[32], py[32], pz[32];
#pragma unroll
        for (int i = 0; i < 32; i++) {
            int n = i * 512 + t;
            px[i] = xb[n * 3 + 0];
            py[i] = xb[n * 3 + 1];
            pz[i] = xb[n * 3 + 2];
        }
        seen[t] = 0u;
        __syncthreads();

        if (t == 0) {
            int f = far0[b];
            seen[f >> 5] = 1u << (f & 31);
            float cx = xb[f * 3 + 0], cy = xb[f * 3 + 1], cz = xb[f * 3 + 2];
            cc[0] = cx; cc[1] = cy; cc[2] = cz;
            g_cent[(b * NC + 0) * 3 + 0] = cx;
            g_cent[(b * NC + 0) * 3 + 1] = cy;
            g_cent[(b * NC + 0) * 3 + 2] = cz;
            __threadfence();
            g_fps_pub[b] = 1;
            sdone = 0;
        }
        __syncthreads();

        int cnt = 1;
        for (int it = 1; it < NC; it++) {
            float cx = cc[0], cy = cc[1], cz = cc[2];
            float best = -1.0f; int bn = 0;
            float bx = 0.f, by = 0.f, bz = 0.f;
#pragma unroll
            for (int i = 0; i < 32; i++) {
                float dx = __fsub_rn(px[i], cx);
                float dy = __fsub_rn(py[i], cy);
                float dz = __fsub_rn(pz[i], cz);
                float d = __fadd_rn(__fadd_rn(__fmul_rn(dx, dx), __fmul_rn(dy, dy)),
                                    __fmul_rn(dz, dz));
                int n = i * 512 + t;
                if (d > best) { best = d; bn = n; bx = px[i]; by = py[i]; bz = pz[i]; }
            }
#pragma unroll
            for (int o = 16; o > 0; o >>= 1) {
                float od = __shfl_down_sync(0xffffffffu, best, o);
                int   on = __shfl_down_sync(0xffffffffu, bn,   o);
                float ox = __shfl_down_sync(0xffffffffu, bx,   o);
                float oy = __shfl_down_sync(0xffffffffu, by,   o);
                float oz = __shfl_down_sync(0xffffffffu, bz,   o);
                if (od > best || (od == best && on < bn)) {
                    best = od; bn = on; bx = ox; by = oy; bz = oz;
                }
            }
            if (lane == 0) { rd[wrp] = best; rn[wrp] = bn; rx[wrp] = bx; ry[wrp] = by; rz[wrp] = bz; }
            __syncthreads();
            if (t < 32) {
                // warp0 shuffle-reduces the 16 partials (no serial LDS scan)
                float pd = (t < 16) ? rd[t] : -1.0f;
                int   pn = (t < 16) ? rn[t] : (1 << 30);
                float pxx = (t < 16) ? rx[t] : 0.f;
                float pyy = (t < 16) ? ry[t] : 0.f;
                float pzz = (t < 16) ? rz[t] : 0.f;
#pragma unroll
                for (int o = 8; o > 0; o >>= 1) {
                    float od = __shfl_down_sync(0xffffffffu, pd, o);
                    int   on = __shfl_down_sync(0xffffffffu, pn, o);
                    float ox = __shfl_down_sync(0xffffffffu, pxx, o);
                    float oy = __shfl_down_sync(0xffffffffu, pyy, o);
                    float oz = __shfl_down_sync(0xffffffffu, pzz, o);
                    if (od > pd || (od == pd && on < pn)) {
                        pd = od; pn = on; pxx = ox; pyy = oy; pzz = oz;
                    }
                }
                if (t == 0) {
                    unsigned bit = 1u << (pn & 31);
                    if (seen[pn >> 5] & bit) {
                        sdone = 1;
                    } else {
                        seen[pn >> 5] |= bit;
                        g_cent[(b * NC + cnt) * 3 + 0] = pxx;
                        g_cent[(b * NC + cnt) * 3 + 1] = pyy;
                        g_cent[(b * NC + cnt) * 3 + 2] = pzz;
                        __threadfence();
                        g_fps_pub[b] = cnt + 1;
                        cc[0] = pxx; cc[1] = pyy; cc[2] = pzz;
                    }
                }
            }
            __syncthreads();
            if (sdone) break;
            cnt++;
        }
        if (t == 0) {
            g_cnt[b] = cnt;
            __threadfence();
            g_fps_done[b] = 1;
        }
    } else {
        // ---------------- consumer-side P0 prep ---------------------------
        if (bid < 2 * NB) {
            const int b = bid - NB;
            g_pool[b * 1024 + t] = 0;
            g_pool[b * 1024 + 512 + t] = 0;
        } else if (bid >= 100) {
            const int wb = bid - 100;
            float s = 0.0f;
            const float4* p1 = (const float4*)fw1;
            for (int i = wb * 512 + t; i < 512 * 256; i += 28 * 512) {
                float4 v = __ldg(p1 + i); s += v.x + v.y + v.z + v.w;
            }
            const float4* p2 = (const float4*)fw2;
            for (int i = wb * 512 + t; i < 256 * 128; i += 28 * 512) {
                float4 v = __ldg(p2 + i); s += v.x + v.y + v.z + v.w;
            }
            const float4* p5 = (const float4*)w5;
            for (int i = wb * 512 + t; i < 1024 * 32; i += 28 * 512) {
                float4 v = __ldg(p5 + i); s += v.x + v.y + v.z + v.w;
            }
            if (t == 0) g_sink[bid] = s;
        }

        // ---------------- P1 consumer: KNN + conv1..4 ---------------------
        int*  hist = (int*)SH;
        unsigned long long* cand = (unsigned long long*)(SH + 16384);
        int*  part = (int*)(SH + 24576);
        float (*Ha)[65] = (float (*)[65])SH;
        float (*Hb)[65] = (float (*)[65])(SH + 8320);
        float* wT = (float*)(SH + 17408);
        float (*P)[4]   = (float (*)[4])(SH + 34048);
        float* W4 = (float*)(SH + 8320);

        // t0-only scanner state (registers): cached per-batch done/cnt
        int nu = bid - NB;
        int doneMask = 0;
        int cntc0 = 0, cntc1 = 0, cntc2 = 0, cntc3 = 0;

        for (;;) {
            if (t == 0) {
                int chosen = -1;
                while (nu < 4 * NC) {
                    int b = nu & 3, ci = nu >> 2;
                    int ok;
                    if (doneMask & (1 << b)) {
                        int cb = (b == 0) ? cntc0 : (b == 1) ? cntc1 : (b == 2) ? cntc2 : cntc3;
                        ok = (ci < cb);
                    } else {
                        for (;;) {
                            int p = g_fps_pub[b];
                            if (p > ci) { ok = 1; break; }
                            if (g_fps_done[b]) {
                                int cb = g_cnt[b];
                                if (b == 0) cntc0 = cb; else if (b == 1) cntc1 = cb;
                                else if (b == 2) cntc2 = cb; else cntc3 = cb;
                                doneMask |= (1 << b);
                                ok = (ci < cb);
                                break;
                            }
                        }
                    }
                    if (ok) { chosen = nu; break; }
                    nu += NCONS;          // invalid: register-speed skip
                }
                s_u = chosen;
                if (chosen >= 0) nu = chosen + NCONS;
            }
            __syncthreads();
            const int cu = s_u;
            __syncthreads();
            if (cu < 0) break;
            const int b = cu & 3, ci = cu >> 2;
            __threadfence();              // acquire: order cent reads after pub

            const float* xb = x + (size_t)b * NPTS * 3;
            const float cx = g_cent[(b * NC + ci) * 3 + 0];
            const float cy = g_cent[(b * NC + ci) * 3 + 1];
            const float cz = g_cent[(b * NC + ci) * 3 + 2];
            const float c2s = __fadd_rn(__fadd_rn(__fmul_rn(cx, cx), __fmul_rn(cy, cy)),
                                        __fmul_rn(cz, cz));
            unsigned uk[32];
#pragma unroll
            for (int i = 0; i < 32; i++) {
                int n = i * 512 + t;
                float X = xb[n * 3 + 0], Y = xb[n * 3 + 1], Z = xb[n * 3 + 2];
                float x2 = __fadd_rn(__fadd_rn(__fmul_rn(X, X), __fmul_rn(Y, Y)),
                                     __fmul_rn(Z, Z));
                float dt = __fadd_rn(__fadd_rn(__fmul_rn(cx, X), __fmul_rn(cy, Y)),
                                     __fmul_rn(cz, Z));
                uk[i] = f_ord(__fsub_rn(__fadd_rn(c2s, x2), __fmul_rn(2.0f, dt)));
            }

            // ---- radix-select: exact 32 smallest (u, idx) ----
#pragma unroll
            for (int i = 0; i < 8; i++) hist[t + 512 * i] = 0;
            if (t == 0) { s_sure = 0; s_cand = 0; }
            __syncthreads();
#pragma unroll
            for (int i = 0; i < 32; i++) atomicAdd(&hist[uk[i] >> 20], 1);
            __syncthreads();
            {
                int ps = 0;
#pragma unroll
                for (int i = 0; i < 8; i++) ps += hist[t * 8 + i];
                part[t] = ps;
            }
            __syncthreads();
            if (t < 32) {
                int seg = 0;
                for (int i = 0; i < 16; i++) seg += part[t * 16 + i];
                int cum = seg;
#pragma unroll
                for (int o = 1; o < 32; o <<= 1) {
                    int v = __shfl_up_sync(0xffffffffu, cum, o);
                    if (lane >= o) cum += v;
                }
                unsigned bal = __ballot_sync(0xffffffffu, cum >= KNN);
                int sel = __ffs(bal) - 1;
                if (t == sel) {
                    int run = cum - seg;
                    int pi = sel * 16;
                    while (run + part[pi] < KNN) { run += part[pi]; pi++; }
                    int bi = pi * 8;
                    while (run + hist[bi] < KNN) { run += hist[bi]; bi++; }
                    s_B = bi; s_m = run;
                }
            }
            __syncthreads();
            const int B = s_B, m = s_m;
#pragma unroll
            for (int i = 0; i < 32; i++) {
                int bkt = (int)(uk[i] >> 20);
                if (bkt < B) {
                    int s = atomicAdd(&s_sure, 1);
                    wlist[s] = (i << 9) + t;
                } else if (bkt == B) {
                    int c = atomicAdd(&s_cand, 1);
                    if (c < CAP)
                        cand[c] = ((unsigned long long)uk[i] << 14) | (unsigned)((i << 9) + t);
                }
            }
            __syncthreads();
            {
                int e = s_cand; if (e > CAP) e = CAP;
                const int need = KNN - m;
                for (int i = t; i < e; i += 512) {
                    unsigned long long k0 = cand[i];
                    int r = 0;
                    for (int j = 0; j < e; j++) r += (cand[j] < k0);
                    if (r < need) wlist[m + r] = (int)(k0 & 0x3FFFull);
                }
            }
            __syncthreads();

            // gather neighbor coords + stage transposed w2
            if (t < KNN) {
                int n = wlist[t];
                P[t][0] = xb[n * 3 + 0];
                P[t][1] = xb[n * 3 + 1];
                P[t][2] = xb[n * 3 + 2];
            }
            for (int k = t; k < 4096; k += 512)
                wT[(k & 63) * 65 + (k >> 6)] = __ldg(w2 + k);
            __syncthreads();

            // conv1: 3 -> 64 (P -> Ha)
            {
                int ch = t & 63, p0 = t >> 6;
                float wa = __ldg(w1 + ch * 3 + 0), wb = __ldg(w1 + ch * 3 + 1),
                      wc = __ldg(w1 + ch * 3 + 2), bb = __ldg(b1 + ch);
#pragma unroll
                for (int k = 0; k < 4; k++) {
                    int p = p0 + 8 * k;
                    float v = fmaf(wa, P[p][0], fmaf(wb, P[p][1], fmaf(wc, P[p][2], bb)));
                    Ha[p][ch] = fmaxf(v, 0.0f);
                }
            }
            __syncthreads();

            // conv2: 64 -> 64 (Ha -> Hb), conflict-free smem weights
            {
                int ch = t & 63, p0 = t >> 6;
                float bb = __ldg(b2 + ch);
                float a0 = bb, a1 = bb, a2 = bb, a3 = bb;
#pragma unroll 8
                for (int j = 0; j < 64; j++) {
                    float ww = wT[j * 65 + ch];
                    a0 = fmaf(ww, Ha[p0 +  0][j], a0);
                    a1 = fmaf(ww, Ha[p0 +  8][j], a1);
                    a2 = fmaf(ww, Ha[p0 + 16][j], a2);
                    a3 = fmaf(ww, Ha[p0 + 24][j], a3);
                }
                Hb[p0 +  0][ch] = fmaxf(a0, 0.0f);
                Hb[p0 +  8][ch] = fmaxf(a1, 0.0f);
                Hb[p0 + 16][ch] = fmaxf(a2, 0.0f);
                Hb[p0 + 24][ch] = fmaxf(a3, 0.0f);
            }
            __syncthreads();

            // stage transposed w3
            for (int k = t; k < 4096; k += 512)
                wT[(k & 63) * 65 + (k >> 6)] = __ldg(w3 + k);
            __syncthreads();

            // conv3: 64 -> 64 (Hb -> Ha)
            {
                int ch = t & 63, p0 = t >> 6;
                float bb = __ldg(b3 + ch);
                float a0 = bb, a1 = bb, a2 = bb, a3 = bb;
#pragma unroll 8
                for (int j = 0; j < 64; j++) {
                    float ww = wT[j * 65 + ch];
                    a0 = fmaf(ww, Hb[p0 +  0][j], a0);
                    a1 = fmaf(ww, Hb[p0 +  8][j], a1);
                    a2 = fmaf(ww, Hb[p0 + 16][j], a2);
                    a3 = fmaf(ww, Hb[p0 + 24][j], a3);
                }
                Ha[p0 +  0][ch] = fmaxf(a0, 0.0f);
                Ha[p0 +  8][ch] = fmaxf(a1, 0.0f);
                Ha[p0 + 16][ch] = fmaxf(a2, 0.0f);
                Ha[p0 + 24][ch] = fmaxf(a3, 0.0f);
            }
            __syncthreads();

            // stage w4 (padded rows; Hb/wT dead)
            for (int k = t; k < 8192; k += 512)
                W4[(k >> 6) * 65 + (k & 63)] = __ldg(w4 + k);
            __syncthreads();

            // conv4: 64 -> 128 (Ha -> g_h4, coalesced)
            {
                int oc = t & 127, p0 = t >> 7;
                float bb = __ldg(b4 + oc);
                float acc[8];
#pragma unroll
                for (int k = 0; k < 8; k++) acc[k] = bb;
#pragma unroll 4
                for (int j = 0; j < 64; j++) {
                    float ww = W4[oc * 65 + j];
#pragma unroll
                    for (int k = 0; k < 8; k++)
                        acc[k] = fmaf(ww, Ha[p0 + 4 * k][j], acc[k]);
                }
                float* oo = g_h4 + (size_t)(b * NC + ci) * KNN * 128;
#pragma unroll
                for (int k = 0; k < 8; k++)
                    oo[(p0 + 4 * k) * 128 + oc] = fmaxf(acc[k], 0.0f);
            }
            __syncthreads();
        }
    }
    grid_bar();   // barrier A

    const int c0 = g_cnt[0], c1 = g_cnt[1], c2 = g_cnt[2], c3 = g_cnt[3];
    const int o1 = c0, o2 = c0 + c1, o3 = o2 + c2;
    const int T = o3 + c3;

    // ============================ P2: conv5 + maxpool =====================
    {
        float* H4 = (float*)SH;
        float* W  = (float*)(SH + 16384);
        float* S  = (float*)(SH + 32896);

        const int nwork = T * 32;
        for (int u = bid; u < nwork; u += G) {
            const int v = u >> 5, z = u & 31;
            int b, base;
            if (v < o1)      { b = 0; base = 0;  }
            else if (v < o2) { b = 1; base = o1; }
            else if (v < o3) { b = 2; base = o2; }
            else             { b = 3; base = o3; }
            const int ci = v - base;

            const float4* h4 = (const float4*)(g_h4 + (size_t)(b * NC + ci) * KNN * 128);
            float4* H4v = (float4*)H4;
            for (int i = t; i < 1024; i += 512) H4v[i] = h4[i];
            const float* wsrc = w5 + (size_t)(z * 32) * 128;
            for (int k = t; k < 4096; k += 512) {
                int r = k >> 7, j = k & 127;
                W[r * 129 + j] = __ldg(wsrc + k);
            }
            __syncthreads();

            const int ocl = t & 31, pg = t >> 5;
            const float* Wr = W + ocl * 129;
            const int p0 = pg * 2;
            float a0 = 0.f, a1 = 0.f;
#pragma unroll 8
            for (int j = 0; j < 128; j++) {
                float ww = Wr[j];
                a0 = fmaf(ww, H4[(p0 + 0) * 128 + j], a0);
                a1 = fmaf(ww, H4[(p0 + 1) * 128 + j], a1);
            }
            S[pg * 32 + ocl] = fmaxf(a0, a1);
            __syncthreads();
            if (t < 32) {
                float mm = S[t];
#pragma unroll
                for (int g = 1; g < 16; g++) mm = fmaxf(mm, S[g * 32 + t]);
                mm = fmaxf(mm + __ldg(b5 + z * 32 + t), 0.0f);
                atomicMax(&g_pool[b * 1024 + z * 32 + t], __float_as_int(mm));
            }
            __syncthreads();
        }
    }
    grid_bar();   // barrier B

    // ============================ P3: fc1 (warp per neuron) ===============
    {
        const int gw = bid * 16 + wrp;
        const int o = gw >> 2, b = gw & 3;
        const float4* wr = (const float4*)(fw1 + (size_t)o * 1024);
        float s = 0.0f;
#pragma unroll
        for (int k = 0; k < 8; k++) {
            int i = lane + 32 * k;
            float4 ww = __ldg(wr + i);
            float g0 = __int_as_float(g_pool[b * 1024 + 4 * i + 0]);
            float g1 = __int_as_float(g_pool[b * 1024 + 4 * i + 1]);
            float g2 = __int_as_float(g_pool[b * 1024 + 4 * i + 2]);
            float g3 = __int_as_float(g_pool[b * 1024 + 4 * i + 3]);
            s = fmaf(ww.x, g0, fmaf(ww.y, g1, fmaf(ww.z, g2, fmaf(ww.w, g3, s))));
        }
#pragma unroll
        for (int off = 16; off > 0; off >>= 1)
            s += __shfl_xor_sync(0xffffffffu, s, off);
        if (lane == 0) g_a1[b * 512 + o] = fmaxf(s + __ldg(fb1 + o), 0.0f);
    }
    grid_bar();   // barrier C

    // ============================ P4: fc2 =================================
    {
        const int gw = bid * 16 + wrp;
        if (gw < 1024) {
            const int o = gw >> 2, b = gw & 3;
            const float4* wr = (const float4*)(fw2 + (size_t)o * 512);
            const float* a1p = g_a1 + b * 512;
            float s = 0.0f;
#pragma unroll
            for (int k = 0; k < 4; k++) {
                int i = lane + 32 * k;
                float4 ww = __ldg(wr + i);
                s = fmaf(ww.x, a1p[4 * i + 0], fmaf(ww.y, a1p[4 * i + 1],
                    fmaf(ww.z, a1p[4 * i + 2], fmaf(ww.w, a1p[4 * i + 3], s))));
            }
#pragma unroll
            for (int off = 16; off > 0; off >>= 1)
                s += __shfl_xor_sync(0xffffffffu, s, off);
            if (lane == 0) g_a2[b * 256 + o] = fmaxf(s + __ldg(fb2 + o), 0.0f);
        }
    }
    grid_bar();   // barrier D

    // ============================ P5: fc3 -> out ==========================
    {
        const int gw = bid * 16 + wrp;
        if (gw < 12) {
            const int o = gw >> 2, b = gw & 3;
            const float4* wr = (const float4*)(fw3 + (size_t)o * 256);
            const float* a2p = g_a2 + b * 256;
            float s = 0.0f;
#pragma unroll
            for (int k = 0; k < 2; k++) {
                int i = lane + 32 * k;
                float4 ww = __ldg(wr + i);
                s = fmaf(ww.x, a2p[4 * i + 0], fmaf(ww.y, a2p[4 * i + 1],
                    fmaf(ww.z, a2p[4 * i + 2], fmaf(ww.w, a2p[4 * i + 3], s))));
            }
#pragma unroll
            for (int off = 16; off > 0; off >>= 1)
                s += __shfl_xor_sync(0xffffffffu, s, off);
            if (lane == 0) out[b * 3 + o] = s + __ldg(fb3 + o);
        }
    }
}

// ===========================================================================
extern "C" void kernel_launch(void* const* d_in, const int* in_sizes, int n_in,
                              void* d_out, int out_size) {
    const float* x    = (const float*)d_in[0];
    const int*   far0 = (const int*)d_in[1];
    const float* w1 = (const float*)d_in[2];  const float* b1 = (const float*)d_in[3];
    const float* w2 = (const float*)d_in[4];  const float* b2 = (const float*)d_in[5];
    const float* w3 = (const float*)d_in[6];  const float* b3 = (const float*)d_in[7];
    const float* w4 = (const float*)d_in[8];  const float* b4 = (const float*)d_in[9];
    const float* w5 = (const float*)d_in[10]; const float* b5 = (const float*)d_in[11];
    const float* fw1 = (const float*)d_in[12]; const float* fb1 = (const float*)d_in[13];
    const float* fw2 = (const float*)d_in[14]; const float* fb2 = (const float*)d_in[15];
    const float* fw3 = (const float*)d_in[16]; const float* fb3 = (const float*)d_in[17];
    float* out = (float*)d_out;

    k_all<<<G, 512>>>(x, far0, w1, b1, w2, b2, w3, b3, w4, b4, w5, b5,
                      fw1, fb1, fw2, fb2, fw3, fb3, out);
}

// round 16
// speedup vs baseline: 1.0530x; 1.0530x over previous
#include <cuda_runtime.h>
#include <cuda_bf16.h>
#include <cstdint>

// ---------------------------------------------------------------------------
// cls_model, persistent single-kernel. B=4, N=16384, C=3, N_C=1024, K=32
// R15: exact R11 (last passing) kernel, with ONLY the L2 warm-up blocks
//      removed (they cold-streamed 3MB before barrier A on the critical path).
// Phases: P0 FPS (progressive pub) || pool-zero ; P1 KNN+conv1..4 ; barA ;
//         P2 conv5+maxpool ; barB ; P3 fc1 ; barC ; P4 fc2 ; barD ; P5 fc3
// ---------------------------------------------------------------------------

#define NB 4
#define NPTS 16384
#define NC 1024
#define KNN 32
#define G 128
#define NCONS 124
#define CAP 1024

// ---- device scratch (no allocations allowed) ----
__device__ int      g_cnt[NB];
__device__ float    g_cent[NB * NC * 3];
__device__ float    g_h4[(size_t)NB * NC * KNN * 128];
__device__ int      g_pool[NB * 1024];
__device__ float    g_a1[NB * 512];
__device__ float    g_a2[NB * 256];
__device__ volatile int g_fps_pub[NB];
__device__ volatile int g_fps_done[NB];
__device__ unsigned g_bar_arrive = 0;
__device__ unsigned g_bar_gen = 0;

static __device__ __forceinline__ unsigned f_ord(float f) {
    unsigned b = __float_as_uint(f);
    return b ^ ((unsigned)(((int)b) >> 31) | 0x80000000u);
}

static __device__ __forceinline__ void grid_bar() {
    __syncthreads();
    if (threadIdx.x == 0) {
        unsigned gen = ((volatile unsigned*)&g_bar_gen)[0];
        __threadfence();
        unsigned a = atomicAdd(&g_bar_arrive, 1u);
        if (a == (unsigned)G - 1u) {
            g_bar_arrive = 0u;
            __threadfence();
            atomicAdd(&g_bar_gen, 1u);
        } else {
            while (((volatile unsigned*)&g_bar_gen)[0] == gen) __nanosleep(32);
        }
        __threadfence();
    }
    __syncthreads();
}

// SMEM overlay (phases sequential; offsets in bytes):
//  FPS:  seen[512] u32 @0
//  KNN:  hist[4096]i @0 (16384) | cand[CAP]u64 @16384 (8192) | part[512]i @24576
//  conv: Ha[32][65] @0 | Hb[32][65] @8320 | wT[64*65] @17408 | P[32][4] @34048
//        W4[128*65] @8320 (Hb/wT dead by conv4)
//  P2:   H4[32*128] @0 | W[32*129] @16384 | S[16*32] @32896
#define SH_BYTES 41728
__shared__ __align__(16) char SH[SH_BYTES];

__global__ __launch_bounds__(512) void k_all(
    const float* __restrict__ x,    const int* __restrict__ far0,
    const float* __restrict__ w1,  const float* __restrict__ b1,
    const float* __restrict__ w2,  const float* __restrict__ b2,
    const float* __restrict__ w3,  const float* __restrict__ b3,
    const float* __restrict__ w4,  const float* __restrict__ b4,
    const float* __restrict__ w5,  const float* __restrict__ b5,
    const float* __restrict__ fw1, const float* __restrict__ fb1,
    const float* __restrict__ fw2, const float* __restrict__ fb2,
    const float* __restrict__ fw3, const float* __restrict__ fb3,
    float* __restrict__ out) {
    const int bid = blockIdx.x;
    const int t = threadIdx.x;
    const int lane = t & 31, wrp = t >> 5;

    __shared__ float cc[3];
    __shared__ float rd[16]; __shared__ int rn[16];
    __shared__ float rx[16], ry[16], rz[16];
    __shared__ int sdone;
    __shared__ int wlist[KNN];
    __shared__ int s_u, s_B, s_m, s_sure, s_cand;

    // ================= P0/P1 overlapped ===================================
    if (bid < NB) {
        // ---------------- FPS producer (bit-exact vs reference) -----------
        const int b = bid;
        const float* xb = x + (size_t)b * NPTS * 3;
        unsigned* seen = (unsigned*)SH;

        if (t == 0) { g_fps_done[b] = 0; g_fps_pub[b] = 0; __threadfence(); }

        float px[32], py[32], pz[32];
#pragma unroll
        for (int i = 0; i < 32; i++) {
            int n = i * 512 + t;
            px[i] = xb[n * 3 + 0];
            py[i] = xb[n * 3 + 1];
            pz[i] = xb[n * 3 + 2];
        }
        seen[t] = 0u;
        __syncthreads();

        if (t == 0) {
            int f = far0[b];
            seen[f >> 5] = 1u << (f & 31);
            float cx = xb[f * 3 + 0], cy = xb[f * 3 + 1], cz = xb[f * 3 + 2];
            cc[0] = cx; cc[1] = cy; cc[2] = cz;
            g_cent[(b * NC + 0) * 3 + 0] = cx;
            g_cent[(b * NC + 0) * 3 + 1] = cy;
            g_cent[(b * NC + 0) * 3 + 2] = cz;
            __threadfence();
            g_fps_pub[b] = 1;
            sdone = 0;
        }
        __syncthreads();

        int cnt = 1;
        for (int it = 1; it < NC; it++) {
            float cx = cc[0], cy = cc[1], cz = cc[2];
            float best = -1.0f; int bn = 0;
            float bx = 0.f, by = 0.f, bz = 0.f;
#pragma unroll
            for (int i = 0; i < 32; i++) {
                float dx = __fsub_rn(px[i], cx);
                float dy = __fsub_rn(py[i], cy);
                float dz = __fsub_rn(pz[i], cz);
                float d = __fadd_rn(__fadd_rn(__fmul_rn(dx, dx), __fmul_rn(dy, dy)),
                                    __fmul_rn(dz, dz));
                int n = i * 512 + t;
                if (d > best) { best = d; bn = n; bx = px[i]; by = py[i]; bz = pz[i]; }
            }
#pragma unroll
            for (int o = 16; o > 0; o >>= 1) {
                float od = __shfl_down_sync(0xffffffffu, best, o);
                int   on = __shfl_down_sync(0xffffffffu, bn,   o);
                float ox = __shfl_down_sync(0xffffffffu, bx,   o);
                float oy = __shfl_down_sync(0xffffffffu, by,   o);
                float oz = __shfl_down_sync(0xffffffffu, bz,   o);
                if (od > best || (od == best && on < bn)) {
                    best = od; bn = on; bx = ox; by = oy; bz = oz;
                }
            }
            if (lane == 0) { rd[wrp] = best; rn[wrp] = bn; rx[wrp] = bx; ry[wrp] = by; rz[wrp] = bz; }
            __syncthreads();
            if (t < 32) {
                float pd = (t < 16) ? rd[t] : -1.0f;
                int   pn = (t < 16) ? rn[t] : (1 << 30);
                float pxx = (t < 16) ? rx[t] : 0.f;
                float pyy = (t < 16) ? ry[t] : 0.f;
                float pzz = (t < 16) ? rz[t] : 0.f;
#pragma unroll
                for (int o = 8; o > 0; o >>= 1) {
                    float od = __shfl_down_sync(0xffffffffu, pd, o);
                    int   on = __shfl_down_sync(0xffffffffu, pn, o);
                    float ox = __shfl_down_sync(0xffffffffu, pxx, o);
                    float oy = __shfl_down_sync(0xffffffffu, pyy, o);
                    float oz = __shfl_down_sync(0xffffffffu, pzz, o);
                    if (od > pd || (od == pd && on < pn)) {
                        pd = od; pn = on; pxx = ox; pyy = oy; pzz = oz;
                    }
                }
                if (t == 0) {
                    unsigned bit = 1u << (pn & 31);
                    if (seen[pn >> 5] & bit) {
                        sdone = 1;
                    } else {
                        seen[pn >> 5] |= bit;
                        g_cent[(b * NC + cnt) * 3 + 0] = pxx;
                        g_cent[(b * NC + cnt) * 3 + 1] = pyy;
                        g_cent[(b * NC + cnt) * 3 + 2] = pzz;
                        __threadfence();
                        g_fps_pub[b] = cnt + 1;
                        cc[0] = pxx; cc[1] = pyy; cc[2] = pzz;
                    }
                }
            }
            __syncthreads();
            if (sdone) break;
            cnt++;
        }
        if (t == 0) {
            g_cnt[b] = cnt;
            __threadfence();
            g_fps_done[b] = 1;
        }
    } else {
        // ---------------- consumer-side P0 prep ---------------------------
        if (bid < 2 * NB) {
            const int b = bid - NB;
            g_pool[b * 1024 + t] = 0;
            g_pool[b * 1024 + 512 + t] = 0;
        }

        // ---------------- P1 consumer: KNN + conv1..4 ---------------------
        int*  hist = (int*)SH;
        unsigned long long* cand = (unsigned long long*)(SH + 16384);
        int*  part = (int*)(SH + 24576);
        float (*Ha)[65] = (float (*)[65])SH;
        float (*Hb)[65] = (float (*)[65])(SH + 8320);
        float* wT = (float*)(SH + 17408);
        float (*P)[4]   = (float (*)[4])(SH + 34048);
        float* W4 = (float*)(SH + 8320);

        int nu = bid - NB;
        int doneMask = 0;
        int cntc0 = 0, cntc1 = 0, cntc2 = 0, cntc3 = 0;

        for (;;) {
            if (t == 0) {
                int chosen = -1;
                while (nu < 4 * NC) {
                    int b = nu & 3, ci = nu >> 2;
                    int ok;
                    if (doneMask & (1 << b)) {
                        int cb = (b == 0) ? cntc0 : (b == 1) ? cntc1 : (b == 2) ? cntc2 : cntc3;
                        ok = (ci < cb);
                    } else {
                        for (;;) {
                            int p = g_fps_pub[b];
                            if (p > ci) { ok = 1; break; }
                            if (g_fps_done[b]) {
                                int cb = g_cnt[b];
                                if (b == 0) cntc0 = cb; else if (b == 1) cntc1 = cb;
                                else if (b == 2) cntc2 = cb; else cntc3 = cb;
                                doneMask |= (1 << b);
                                ok = (ci < cb);
                                break;
                            }
                        }
                    }
                    if (ok) { chosen = nu; break; }
                    nu += NCONS;
                }
                s_u = chosen;
                if (chosen >= 0) nu = chosen + NCONS;
            }
            __syncthreads();
            const int cu = s_u;
            __syncthreads();
            if (cu < 0) break;
            const int b = cu & 3, ci = cu >> 2;
            __threadfence();

            const float* xb = x + (size_t)b * NPTS * 3;
            const float cx = g_cent[(b * NC + ci) * 3 + 0];
            const float cy = g_cent[(b * NC + ci) * 3 + 1];
            const float cz = g_cent[(b * NC + ci) * 3 + 2];
            const float c2s = __fadd_rn(__fadd_rn(__fmul_rn(cx, cx), __fmul_rn(cy, cy)),
                                        __fmul_rn(cz, cz));
            unsigned uk[32];
#pragma unroll
            for (int i = 0; i < 32; i++) {
                int n = i * 512 + t;
                float X = xb[n * 3 + 0], Y = xb[n * 3 + 1], Z = xb[n * 3 + 2];
                float x2 = __fadd_rn(__fadd_rn(__fmul_rn(X, X), __fmul_rn(Y, Y)),
                                     __fmul_rn(Z, Z));
                float dt = __fadd_rn(__fadd_rn(__fmul_rn(cx, X), __fmul_rn(cy, Y)),
                                     __fmul_rn(cz, Z));
                uk[i] = f_ord(__fsub_rn(__fadd_rn(c2s, x2), __fmul_rn(2.0f, dt)));
            }

            // ---- radix-select: exact 32 smallest (u, idx) ----
#pragma unroll
            for (int i = 0; i < 8; i++) hist[t + 512 * i] = 0;
            if (t == 0) { s_sure = 0; s_cand = 0; }
            __syncthreads();
#pragma unroll
            for (int i = 0; i < 32; i++) atomicAdd(&hist[uk[i] >> 20], 1);
            __syncthreads();
            {
                int ps = 0;
#pragma unroll
                for (int i = 0; i < 8; i++) ps += hist[t * 8 + i];
                part[t] = ps;
            }
            __syncthreads();
            if (t < 32) {
                int seg = 0;
                for (int i = 0; i < 16; i++) seg += part[t * 16 + i];
                int cum = seg;
#pragma unroll
                for (int o = 1; o < 32; o <<= 1) {
                    int v = __shfl_up_sync(0xffffffffu, cum, o);
                    if (lane >= o) cum += v;
                }
                unsigned bal = __ballot_sync(0xffffffffu, cum >= KNN);
                int sel = __ffs(bal) - 1;
                if (t == sel) {
                    int run = cum - seg;
                    int pi = sel * 16;
                    while (run + part[pi] < KNN) { run += part[pi]; pi++; }
                    int bi = pi * 8;
                    while (run + hist[bi] < KNN) { run += hist[bi]; bi++; }
                    s_B = bi; s_m = run;
                }
            }
            __syncthreads();
            const int B = s_B, m = s_m;
#pragma unroll
            for (int i = 0; i < 32; i++) {
                int bkt = (int)(uk[i] >> 20);
                if (bkt < B) {
                    int s = atomicAdd(&s_sure, 1);
                    wlist[s] = (i << 9) + t;
                } else if (bkt == B) {
                    int c = atomicAdd(&s_cand, 1);
                    if (c < CAP)
                        cand[c] = ((unsigned long long)uk[i] << 14) | (unsigned)((i << 9) + t);
                }
            }
            __syncthreads();
            {
                int e = s_cand; if (e > CAP) e = CAP;
                const int need = KNN - m;
                for (int i = t; i < e; i += 512) {
                    unsigned long long k0 = cand[i];
                    int r = 0;
                    for (int j = 0; j < e; j++) r += (cand[j] < k0);
                    if (r < need) wlist[m + r] = (int)(k0 & 0x3FFFull);
                }
            }
            __syncthreads();

            // gather neighbor coords + stage transposed w2
            if (t < KNN) {
                int n = wlist[t];
                P[t][0] = xb[n * 3 + 0];
                P[t][1] = xb[n * 3 + 1];
                P[t][2] = xb[n * 3 + 2];
            }
            for (int k = t; k < 4096; k += 512)
                wT[(k & 63) * 65 + (k >> 6)] = __ldg(w2 + k);
            __syncthreads();

            // conv1: 3 -> 64 (P -> Ha)
            {
                int ch = t & 63, p0 = t >> 6;
                float wa = __ldg(w1 + ch * 3 + 0), wb = __ldg(w1 + ch * 3 + 1),
                      wc = __ldg(w1 + ch * 3 + 2), bb = __ldg(b1 + ch);
#pragma unroll
                for (int k = 0; k < 4; k++) {
                    int p = p0 + 8 * k;
                    float v = fmaf(wa, P[p][0], fmaf(wb, P[p][1], fmaf(wc, P[p][2], bb)));
                    Ha[p][ch] = fmaxf(v, 0.0f);
                }
            }
            __syncthreads();

            // conv2: 64 -> 64 (Ha -> Hb), conflict-free smem weights
            {
                int ch = t & 63, p0 = t >> 6;
                float bb = __ldg(b2 + ch);
                float a0 = bb, a1 = bb, a2 = bb, a3 = bb;
#pragma unroll 8
                for (int j = 0; j < 64; j++) {
                    float ww = wT[j * 65 + ch];
                    a0 = fmaf(ww, Ha[p0 +  0][j], a0);
                    a1 = fmaf(ww, Ha[p0 +  8][j], a1);
                    a2 = fmaf(ww, Ha[p0 + 16][j], a2);
                    a3 = fmaf(ww, Ha[p0 + 24][j], a3);
                }
                Hb[p0 +  0][ch] = fmaxf(a0, 0.0f);
                Hb[p0 +  8][ch] = fmaxf(a1, 0.0f);
                Hb[p0 + 16][ch] = fmaxf(a2, 0.0f);
                Hb[p0 + 24][ch] = fmaxf(a3, 0.0f);
            }
            __syncthreads();

            // stage transposed w3
            for (int k = t; k < 4096; k += 512)
                wT[(k & 63) * 65 + (k >> 6)] = __ldg(w3 + k);
            __syncthreads();

            // conv3: 64 -> 64 (Hb -> Ha)
            {
                int ch = t & 63, p0 = t >> 6;
                float bb = __ldg(b3 + ch);
                float a0 = bb, a1 = bb, a2 = bb, a3 = bb;
#pragma unroll 8
                for (int j = 0; j < 64; j++) {
                    float ww = wT[j * 65 + ch];
                    a0 = fmaf(ww, Hb[p0 +  0][j], a0);
                    a1 = fmaf(ww, Hb[p0 +  8][j], a1);
                    a2 = fmaf(ww, Hb[p0 + 16][j], a2);
                    a3 = fmaf(ww, Hb[p0 + 24][j], a3);
                }
                Ha[p0 +  0][ch] = fmaxf(a0, 0.0f);
                Ha[p0 +  8][ch] = fmaxf(a1, 0.0f);
                Ha[p0 + 16][ch] = fmaxf(a2, 0.0f);
                Ha[p0 + 24][ch] = fmaxf(a3, 0.0f);
            }
            __syncthreads();

            // stage w4 (padded rows; Hb/wT dead)
            for (int k = t; k < 8192; k += 512)
                W4[(k >> 6) * 65 + (k & 63)] = __ldg(w4 + k);
            __syncthreads();

            // conv4: 64 -> 128 (Ha -> g_h4, coalesced)
            {
                int oc = t & 127, p0 = t >> 7;
                float bb = __ldg(b4 + oc);
                float acc[8];
#pragma unroll
                for (int k = 0; k < 8; k++) acc[k] = bb;
#pragma unroll 4
                for (int j = 0; j < 64; j++) {
                    float ww = W4[oc * 65 + j];
#pragma unroll
                    for (int k = 0; k < 8; k++)
                        acc[k] = fmaf(ww, Ha[p0 + 4 * k][j], acc[k]);
                }
                float* oo = g_h4 + (size_t)(b * NC + ci) * KNN * 128;
#pragma unroll
                for (int k = 0; k < 8; k++)
                    oo[(p0 + 4 * k) * 128 + oc] = fmaxf(acc[k], 0.0f);
            }
            __syncthreads();
        }
    }
    grid_bar();   // barrier A

    const int c0 = g_cnt[0], c1 = g_cnt[1], c2 = g_cnt[2], c3 = g_cnt[3];
    const int o1 = c0, o2 = c0 + c1, o3 = o2 + c2;
    const int T = o3 + c3;

    // ============================ P2: conv5 + maxpool =====================
    {
        float* H4 = (float*)SH;
        float* W  = (float*)(SH + 16384);
        float* S  = (float*)(SH + 32896);

        const int nwork = T * 32;
        for (int u = bid; u < nwork; u += G) {
            const int v = u >> 5, z = u & 31;
            int b, base;
            if (v < o1)      { b = 0; base = 0;  }
            else if (v < o2) { b = 1; base = o1; }
            else if (v < o3) { b = 2; base = o2; }
            else             { b = 3; base = o3; }
            const int ci = v - base;

            const float4* h4 = (const float4*)(g_h4 + (size_t)(b * NC + ci) * KNN * 128);
            float4* H4v = (float4*)H4;
            for (int i = t; i < 1024; i += 512) H4v[i] = h4[i];
            const float* wsrc = w5 + (size_t)(z * 32) * 128;
            for (int k = t; k < 4096; k += 512) {
                int r = k >> 7, j = k & 127;
                W[r * 129 + j] = __ldg(wsrc + k);
            }
            __syncthreads();

            const int ocl = t & 31, pg = t >> 5;
            const float* Wr = W + ocl * 129;
            const int p0 = pg * 2;
            float a0 = 0.f, a1 = 0.f;
#pragma unroll 8
            for (int j = 0; j < 128; j++) {
                float ww = Wr[j];
                a0 = fmaf(ww, H4[(p0 + 0) * 128 + j], a0);
                a1 = fmaf(ww, H4[(p0 + 1) * 128 + j], a1);
            }
            S[pg * 32 + ocl] = fmaxf(a0, a1);
            __syncthreads();
            if (t < 32) {
                float mm = S[t];
#pragma unroll
                for (int g = 1; g < 16; g++) mm = fmaxf(mm, S[g * 32 + t]);
                mm = fmaxf(mm + __ldg(b5 + z * 32 + t), 0.0f);
                atomicMax(&g_pool[b * 1024 + z * 32 + t], __float_as_int(mm));
            }
            __syncthreads();
        }
    }
    grid_bar();   // barrier B

    // ============================ P3: fc1 (warp per neuron) ===============
    {
        const int gw = bid * 16 + wrp;
        const int o = gw >> 2, b = gw & 3;
        const float4* wr = (const float4*)(fw1 + (size_t)o * 1024);
        float s = 0.0f;
#pragma unroll
        for (int k = 0; k < 8; k++) {
            int i = lane + 32 * k;
            float4 ww = __ldg(wr + i);
            float g0 = __int_as_float(g_pool[b * 1024 + 4 * i + 0]);
            float g1 = __int_as_float(g_pool[b * 1024 + 4 * i + 1]);
            float g2 = __int_as_float(g_pool[b * 1024 + 4 * i + 2]);
            float g3 = __int_as_float(g_pool[b * 1024 + 4 * i + 3]);
            s = fmaf(ww.x, g0, fmaf(ww.y, g1, fmaf(ww.z, g2, fmaf(ww.w, g3, s))));
        }
#pragma unroll
        for (int off = 16; off > 0; off >>= 1)
            s += __shfl_xor_sync(0xffffffffu, s, off);
        if (lane == 0) g_a1[b * 512 + o] = fmaxf(s + __ldg(fb1 + o), 0.0f);
    }
    grid_bar();   // barrier C

    // ============================ P4: fc2 =================================
    {
        const int gw = bid * 16 + wrp;
        if (gw < 1024) {
            const int o = gw >> 2, b = gw & 3;
            const float4* wr = (const float4*)(fw2 + (size_t)o * 512);
            const float* a1p = g_a1 + b * 512;
            float s = 0.0f;
#pragma unroll
            for (int k = 0; k < 4; k++) {
                int i = lane + 32 * k;
                float4 ww = __ldg(wr + i);
                s = fmaf(ww.x, a1p[4 * i + 0], fmaf(ww.y, a1p[4 * i + 1],
                    fmaf(ww.z, a1p[4 * i + 2], fmaf(ww.w, a1p[4 * i + 3], s))));
            }
#pragma unroll
            for (int off = 16; off > 0; off >>= 1)
                s += __shfl_xor_sync(0xffffffffu, s, off);
            if (lane == 0) g_a2[b * 256 + o] = fmaxf(s + __ldg(fb2 + o), 0.0f);
        }
    }
    grid_bar();   // barrier D

    // ============================ P5: fc3 -> out ==========================
    {
        const int gw = bid * 16 + wrp;
        if (gw < 12) {
            const int o = gw >> 2, b = gw & 3;
            const float4* wr = (const float4*)(fw3 + (size_t)o * 256);
            const float* a2p = g_a2 + b * 256;
            float s = 0.0f;
#pragma unroll
            for (int k = 0; k < 2; k++) {
                int i = lane + 32 * k;
                float4 ww = __ldg(wr + i);
                s = fmaf(ww.x, a2p[4 * i + 0], fmaf(ww.y, a2p[4 * i + 1],
                    fmaf(ww.z, a2p[4 * i + 2], fmaf(ww.w, a2p[4 * i + 3], s))));
            }
#pragma unroll
            for (int off = 16; off > 0; off >>= 1)
                s += __shfl_xor_sync(0xffffffffu, s, off);
            if (lane == 0) out[b * 3 + o] = s + __ldg(fb3 + o);
        }
    }
}

// ===========================================================================
extern "C" void kernel_launch(void* const* d_in, const int* in_sizes, int n_in,
                              void* d_out, int out_size) {
    const float* x    = (const float*)d_in[0];
    const int*   far0 = (const int*)d_in[1];
    const float* w1 = (const float*)d_in[2];  const float* b1 = (const float*)d_in[3];
    const float* w2 = (const float*)d_in[4];  const float* b2 = (const float*)d_in[5];
    const float* w3 = (const float*)d_in[6];  const float* b3 = (const float*)d_in[7];
    const float* w4 = (const float*)d_in[8];  const float* b4 = (const float*)d_in[9];
    const float* w5 = (const float*)d_in[10]; const float* b5 = (const float*)d_in[11];
    const float* fw1 = (const float*)d_in[12]; const float* fb1 = (const float*)d_in[13];
    const float* fw2 = (const float*)d_in[14]; const float* fb2 = (const float*)d_in[15];
    const float* fw3 = (const float*)d_in[16]; const float* fb3 = (const float*)d_in[17];
    float* out = (float*)d_out;

    k_all<<<G, 512>>>(x, far0, w1, b1, w2, b2, w3, b3, w4, b4, w5, b5,
                      fw1, fb1, fw2, fb2, fw3, fb3, out);
}